// round 14
// baseline (speedup 1.0000x reference)
#include <cuda_runtime.h>
#include <cuda_fp16.h>
#include <math.h>
#include <stdint.h>

#define N_NODES 100000
#define F_IN    512
#define HID     128
#define CLS     64
#define E_MAX   1600000

// ---------------- scratch (no cudaMalloc allowed) ----------------
__device__ __half g_h1h [(size_t)N_NODES * HID]; // h1 = x@W1 (UNSCALED), fp16
__device__ __half g_acc1[(size_t)N_NODES * HID]; // a1 = relu(inv*sum + b1), fp16
__device__ __half g_h2h [(size_t)N_NODES * CLS]; // g2 = inv*(a1@W2), fp16
__device__ __half g_W1t[(size_t)HID * F_IN];     // W1 transposed, n-major, fp16
__device__ __half g_W2t[(size_t)CLS * HID];      // W2 transposed, n-major, fp16
__device__ float  g_inv [N_NODES];
__device__ int    g_cnt [N_NODES];
__device__ int    g_rowstart[N_NODES + 1];
__device__ int    g_cursor[N_NODES];
__device__ int    g_blksum[256];
__device__ int    g_blkoff[256];
__device__ int    g_esrc[E_MAX];

// ---- side stream + fork/join events (static init; not device allocs) ----
struct SideStream {
    cudaStream_t s;
    cudaEvent_t  fork, join;
    SideStream() {
        cudaStreamCreateWithFlags(&s, cudaStreamNonBlocking);
        cudaEventCreateWithFlags(&fork, cudaEventDisableTiming);
        cudaEventCreateWithFlags(&join, cudaEventDisableTiming);
    }
};
static SideStream g_ss;

// ------- weight transpose/convert (default stream) -------
__global__ void k_prepw(const float* __restrict__ W1, const float* __restrict__ W2) {
    int i = blockIdx.x * blockDim.x + threadIdx.x;
    if (i < HID * F_IN) {
        int n = i / F_IN, k = i % F_IN;
        g_W1t[i] = __float2half(W1[(size_t)k * HID + n]);
    }
    if (i < CLS * HID) {
        int n = i / HID, k = i % HID;
        g_W2t[i] = __float2half(W2[(size_t)k * CLS + n]);
    }
}

// ---------------- CSR branch (side stream) ----------------
__global__ void k_zero() {
    int i = blockIdx.x * blockDim.x + threadIdx.x;
    if (i < N_NODES) g_cnt[i] = 0;
}
__global__ void k_hist(const int* __restrict__ dst, int E) {
    int i = (blockIdx.x * blockDim.x + threadIdx.x) * 4;
    if (i + 3 < E) {
        int4 d = *(const int4*)(dst + i);
        atomicAdd(&g_cnt[d.x], 1); atomicAdd(&g_cnt[d.y], 1);
        atomicAdd(&g_cnt[d.z], 1); atomicAdd(&g_cnt[d.w], 1);
    } else {
        for (; i < E; i++) atomicAdd(&g_cnt[dst[i]], 1);
    }
}

#define SCB 512
__global__ void k_scan1(int n) {
    __shared__ int wsum[16];
    int tid = threadIdx.x, lane = tid & 31, wid = tid >> 5;
    int i = blockIdx.x * SCB + tid;
    int v = (i < n) ? g_cnt[i] : 0;
    int x = v;
    #pragma unroll
    for (int o = 1; o < 32; o <<= 1) {
        int t = __shfl_up_sync(0xffffffffu, x, o);
        if (lane >= o) x += t;
    }
    if (lane == 31) wsum[wid] = x;
    __syncthreads();
    if (wid == 0) {
        int s = (lane < 16) ? wsum[lane] : 0;
        #pragma unroll
        for (int o = 1; o < 16; o <<= 1) {
            int t = __shfl_up_sync(0xffffffffu, s, o);
            if (lane >= o) s += t;
        }
        if (lane < 16) wsum[lane] = s;
    }
    __syncthreads();
    int base = (wid > 0) ? wsum[wid - 1] : 0;
    x += base;
    if (i < n) g_rowstart[i] = x - v;
    if (tid == SCB - 1) g_blksum[blockIdx.x] = x;
}
__global__ void k_scan2(int nb) {
    __shared__ int wsum[8];
    int tid = threadIdx.x, lane = tid & 31, wid = tid >> 5;
    int v = (tid < nb) ? g_blksum[tid] : 0;
    int x = v;
    #pragma unroll
    for (int o = 1; o < 32; o <<= 1) {
        int t = __shfl_up_sync(0xffffffffu, x, o);
        if (lane >= o) x += t;
    }
    if (lane == 31) wsum[wid] = x;
    __syncthreads();
    if (wid == 0) {
        int s = (lane < 8) ? wsum[lane] : 0;
        #pragma unroll
        for (int o = 1; o < 8; o <<= 1) {
            int t = __shfl_up_sync(0xffffffffu, s, o);
            if (lane >= o) s += t;
        }
        if (lane < 8) wsum[lane] = s;
    }
    __syncthreads();
    int base = (wid > 0) ? wsum[wid - 1] : 0;
    if (tid < nb) g_blkoff[tid] = x + base - v;
}
__global__ void k_scan3(int n, int E) {
    int i = blockIdx.x * blockDim.x + threadIdx.x;
    if (i < n) {
        int r = g_rowstart[i] + g_blkoff[i / SCB];
        g_rowstart[i] = r;
        g_cursor[i]   = r;
        g_inv[i]      = rsqrtf((float)(1 + g_cnt[i]));
    }
    if (i == 0) g_rowstart[n] = E;
}
__global__ void k_fill(const int* __restrict__ src, const int* __restrict__ dst, int E) {
    int i = (blockIdx.x * blockDim.x + threadIdx.x) * 4;
    if (i + 3 < E) {
        int4 s = *(const int4*)(src + i);
        int4 d = *(const int4*)(dst + i);
        g_esrc[atomicAdd(&g_cursor[d.x], 1)] = s.x;
        g_esrc[atomicAdd(&g_cursor[d.y], 1)] = s.y;
        g_esrc[atomicAdd(&g_cursor[d.z], 1)] = s.z;
        g_esrc[atomicAdd(&g_cursor[d.w], 1)] = s.w;
    } else {
        for (; i < E; i++) g_esrc[atomicAdd(&g_cursor[dst[i]], 1)] = src[i];
    }
}

// ---------------- fp16 mma m16n8k16 + ldmatrix + cp.async ----------------
__device__ __forceinline__ void mma_f16(float* c, uint32_t a0, uint32_t a1,
                                        uint32_t a2, uint32_t a3,
                                        uint32_t b0, uint32_t b1) {
    asm volatile(
        "mma.sync.aligned.m16n8k16.row.col.f32.f16.f16.f32 "
        "{%0,%1,%2,%3}, {%4,%5,%6,%7}, {%8,%9}, {%0,%1,%2,%3};"
        : "+f"(c[0]), "+f"(c[1]), "+f"(c[2]), "+f"(c[3])
        : "r"(a0), "r"(a1), "r"(a2), "r"(a3), "r"(b0), "r"(b1));
}
__device__ __forceinline__ void ldsm4(uint32_t& r0, uint32_t& r1,
                                      uint32_t& r2, uint32_t& r3, uint32_t a) {
    asm volatile("ldmatrix.sync.aligned.m8n8.x4.shared.b16 {%0,%1,%2,%3}, [%4];"
                 : "=r"(r0), "=r"(r1), "=r"(r2), "=r"(r3) : "r"(a));
}
__device__ __forceinline__ void cp16(void* dst, const void* src, bool pred) {
    uint32_t d = (uint32_t)__cvta_generic_to_shared(dst);
    int sz = pred ? 16 : 0;
    asm volatile("cp.async.cg.shared.global [%0],[%1],16,%2;"
                 :: "r"(d), "l"(src), "r"(sz));
}
__device__ __forceinline__ uint32_t packh2(float x, float y) {
    __half2 h = __floats2half2_rn(x, y);
    return *(uint32_t*)&h;
}

// ---- fp16 tensor-core GEMM, 3-stage cp.async pipeline ----
// LAYER==1: A = x fp32 via cp.async (cvt at fragment build), out UNSCALED
// LAYER==2: A = g_acc1 fp16 via cp.async + ldmatrix, out scaled by inv[row]
template<int BM, int BN, int BK, int THREADS, int LAYER>
__global__ __launch_bounds__(THREADS)
void k_mma(const float* __restrict__ Ain, int M, int K)
{
    constexpr bool AH     = (LAYER == 2);
    constexpr int NWARP   = THREADS / 32;
    constexpr int WARPS_N = BN / 64;
    constexpr int WARPS_M = NWARP / WARPS_N;
    constexpr int WM      = BM / WARPS_M;      // 32
    constexpr int RT      = WM / 16;           // 2
    constexpr int PAD     = 8;
    constexpr int ASTR    = BK + PAD;          // elems (float L1, half L2)
    constexpr int BSTR    = BK + PAD;          // halves
    constexpr int STAGES  = 3;
    constexpr int A_STAGE = BM * ASTR * (AH ? 2 : 4);   // bytes
    constexpr int B_STAGE = BN * BSTR * 2;              // bytes
    constexpr int A_CP    = BM*BK*(AH?2:4)/16/THREADS;  // cp.async per thread
    constexpr int B_CP    = BN*BK*2/16/THREADS;

    extern __shared__ __align__(16) char smem_raw[];
    char* aPtr = smem_raw;
    char* bPtr = smem_raw + STAGES * A_STAGE;

    const __half* Asrc = (const __half*)g_acc1;
    const __half* Bt = (LAYER == 1) ? (const __half*)g_W1t : (const __half*)g_W2t;
    __half*       G  = (LAYER == 1) ? (__half*)g_h1h : (__half*)g_h2h;
    const int     N  = BN;

    const int tid  = threadIdx.x;
    const int warp = tid >> 5;
    const int lane = tid & 31;
    const int g    = lane >> 2;
    const int tg   = lane & 3;
    const int wr   = (warp / WARPS_N) * WM;
    const int wc   = (warp % WARPS_N) * 64;
    const int rowBase = blockIdx.x * BM;

    float acc[RT][8][4] = {};

    auto Af = [&](int st, int m, int k) -> float* {
        return (float*)(aPtr + st*A_STAGE) + m*ASTR + k;
    };
    auto Ahp = [&](int st, int m, int k) -> __half* {
        return (__half*)(aPtr + st*A_STAGE) + m*ASTR + k;
    };
    auto Bp = [&](int st, int n, int k) -> __half* {
        return (__half*)(bPtr + st*B_STAGE) + n*BSTR + k;
    };

    auto ldg_tiles = [&](int st, int k0) {
        if constexpr (!AH) {
            #pragma unroll
            for (int i = 0; i < A_CP; i++) {
                int id = tid + i*THREADS;
                int m = id / (BK/4), k4 = id % (BK/4);
                int row = rowBase + m;
                cp16(Af(st, m, k4*4), Ain + (size_t)row*K + k0 + k4*4, row < M);
            }
        } else {
            #pragma unroll
            for (int i = 0; i < A_CP; i++) {
                int id = tid + i*THREADS;
                int m = id / (BK/8), c8 = id % (BK/8);
                int row = rowBase + m;
                cp16(Ahp(st, m, c8*8), Asrc + (size_t)row*K + k0 + c8*8, row < M);
            }
        }
        #pragma unroll
        for (int i = 0; i < B_CP; i++) {
            int id = tid + i*THREADS;
            int n = id / (BK/8), c8 = id % (BK/8);
            cp16(Bp(st, n, c8*8), Bt + (size_t)n*K + k0 + c8*8, true);
        }
    };

    // ldmatrix bases per stage
    const int li = lane & 7, qd = lane >> 3;
    uint32_t bBase[STAGES], aBase[STAGES];
    #pragma unroll
    for (int st = 0; st < STAGES; st++) {
        bBase[st] = (uint32_t)__cvta_generic_to_shared(
            Bp(st, wc + (qd >> 1)*8 + li, (qd & 1)*8));
        if constexpr (AH)
            aBase[st] = (uint32_t)__cvta_generic_to_shared(
                Ahp(st, wr + (qd & 1)*8 + li, (qd >> 1)*8));
    }

    const int KT = K / BK;
    ldg_tiles(0, 0);
    asm volatile("cp.async.commit_group;");
    ldg_tiles(1, BK);
    asm volatile("cp.async.commit_group;");

    for (int kt = 0; kt < KT; kt++) {
        asm volatile("cp.async.wait_group 1;");
        __syncthreads();
        const int st = kt % STAGES;
        if (kt + 2 < KT) ldg_tiles((kt + 2) % STAGES, (kt + 2) * BK);
        asm volatile("cp.async.commit_group;");   // empty group OK at tail

        #pragma unroll
        for (int ks = 0; ks < BK/16; ks++) {
            const int k = ks*16;
            uint32_t bf[8][2];
            #pragma unroll
            for (int p = 0; p < 4; p++)
                ldsm4(bf[2*p][0], bf[2*p][1], bf[2*p+1][0], bf[2*p+1][1],
                      bBase[st] + (uint32_t)((p*16*BSTR + k) * 2));
            #pragma unroll
            for (int rt = 0; rt < RT; rt++) {
                const int r = wr + rt*16;
                uint32_t a0, a1, a2, a3;
                if constexpr (!AH) {
                    float2 f;
                    f = *(float2*)Af(st, r+g,   k + 2*tg);     a0 = packh2(f.x, f.y);
                    f = *(float2*)Af(st, r+g+8, k + 2*tg);     a1 = packh2(f.x, f.y);
                    f = *(float2*)Af(st, r+g,   k + 2*tg + 8); a2 = packh2(f.x, f.y);
                    f = *(float2*)Af(st, r+g+8, k + 2*tg + 8); a3 = packh2(f.x, f.y);
                } else {
                    ldsm4(a0, a1, a2, a3, aBase[st] + (uint32_t)((rt*16*ASTR + k) * 2));
                }
                #pragma unroll
                for (int j = 0; j < 8; j++)
                    mma_f16(acc[rt][j], a0, a1, a2, a3, bf[j][0], bf[j][1]);
            }
        }
        __syncthreads();
    }

    #pragma unroll
    for (int rt = 0; rt < RT; rt++) {
        int r0 = rowBase + wr + rt*16 + g;
        int r1 = r0 + 8;
        float s0, s1;
        if constexpr (LAYER == 1) { s0 = 1.f; s1 = 1.f; }
        else {
            s0 = (r0 < M) ? g_inv[r0] : 0.f;
            s1 = (r1 < M) ? g_inv[r1] : 0.f;
        }
        #pragma unroll
        for (int j = 0; j < 8; j++) {
            int col = wc + j*8 + tg*2;
            if (r0 < M) {
                __half2 v = __floats2half2_rn(acc[rt][j][0]*s0, acc[rt][j][1]*s0);
                *(__half2*)(G + (size_t)r0*N + col) = v;
            }
            if (r1 < M) {
                __half2 v = __floats2half2_rn(acc[rt][j][2]*s1, acc[rt][j][3]*s1);
                *(__half2*)(G + (size_t)r1*N + col) = v;
            }
        }
    }
}

// host-side smem sizes (match k_mma constants)
#define MMA1_SMEM (3 * (128*40*4 + 128*40*2))   // 92160 B
#define MMA2_SMEM (3 * (128*40*2 + 64*40*2))    // 46080 B

// ---------------- fp16 load helpers ----------------
__device__ __forceinline__ float4 ld_h4(const __half* p) {
    uint2 u = *(const uint2*)p;
    float2 a = __half22float2(*(__half2*)&u.x);
    float2 b = __half22float2(*(__half2*)&u.y);
    return make_float4(a.x, a.y, b.x, b.y);
}
__device__ __forceinline__ float2 ld_h2(const __half* p) {
    uint32_t u = *(const uint32_t*)p;
    return __half22float2(*(__half2*)&u);
}

// ---- gather layer 1: a1 = relu(inv[v]*(inv[v]*h[v] + sum inv[s]*h[s]) + b1)
__global__ void k_gather1(const float* __restrict__ b1) {
    int w    = (blockIdx.x * blockDim.x + threadIdx.x) >> 5;
    int lane = threadIdx.x & 31;
    if (w >= N_NODES) return;
    const __half* h = (const __half*)g_h1h;
    float wv = g_inv[w];
    float4 hv = ld_h4(h + (size_t)w*HID + lane*4);
    float4 acc;
    acc.x = wv*hv.x; acc.y = wv*hv.y; acc.z = wv*hv.z; acc.w = wv*hv.w;
    int i   = g_rowstart[w];
    int end = g_rowstart[w+1];
    for (; i + 7 < end; i += 8) {
        #pragma unroll
        for (int u = 0; u < 8; u++) {
            int s = g_esrc[i+u];
            float ws = g_inv[s];
            float4 v = ld_h4(h + (size_t)s*HID + lane*4);
            acc.x = fmaf(ws, v.x, acc.x); acc.y = fmaf(ws, v.y, acc.y);
            acc.z = fmaf(ws, v.z, acc.z); acc.w = fmaf(ws, v.w, acc.w);
        }
    }
    for (; i < end; i++) {
        int s = g_esrc[i];
        float ws = g_inv[s];
        float4 v = ld_h4(h + (size_t)s*HID + lane*4);
        acc.x = fmaf(ws, v.x, acc.x); acc.y = fmaf(ws, v.y, acc.y);
        acc.z = fmaf(ws, v.z, acc.z); acc.w = fmaf(ws, v.w, acc.w);
    }
    float4 bb = *(const float4*)(b1 + lane*4);
    __half2 h0 = __floats2half2_rn(fmaxf(fmaf(wv, acc.x, bb.x), 0.f),
                                   fmaxf(fmaf(wv, acc.y, bb.y), 0.f));
    __half2 h1 = __floats2half2_rn(fmaxf(fmaf(wv, acc.z, bb.z), 0.f),
                                   fmaxf(fmaf(wv, acc.w, bb.w), 0.f));
    uint2 u; u.x = *(uint32_t*)&h0; u.y = *(uint32_t*)&h1;
    *(uint2*)((__half*)g_acc1 + (size_t)w*HID + lane*4) = u;
}

// ---------------- gather layer 2 + log_softmax -> out ----------------------
__global__ void k_gather2(float* __restrict__ out, const float* __restrict__ b2) {
    int w    = (blockIdx.x * blockDim.x + threadIdx.x) >> 5;
    int lane = threadIdx.x & 31;
    if (w >= N_NODES) return;
    const __half* h = (const __half*)g_h2h;
    float2 acc = ld_h2(h + (size_t)w*CLS + lane*2);          // self (g2 scaled)
    int i   = g_rowstart[w];
    int end = g_rowstart[w+1];
    for (; i + 7 < end; i += 8) {
        #pragma unroll
        for (int u = 0; u < 8; u++) {
            int s = g_esrc[i+u];
            float2 v = ld_h2(h + (size_t)s*CLS + lane*2);
            acc.x += v.x; acc.y += v.y;
        }
    }
    for (; i < end; i++) {
        int s = g_esrc[i];
        float2 v = ld_h2(h + (size_t)s*CLS + lane*2);
        acc.x += v.x; acc.y += v.y;
    }
    float sc = g_inv[w];
    float t0 = fmaf(sc, acc.x, b2[lane*2+0]);
    float t1 = fmaf(sc, acc.y, b2[lane*2+1]);
    float m = fmaxf(t0, t1);
    #pragma unroll
    for (int o = 16; o > 0; o >>= 1) m = fmaxf(m, __shfl_xor_sync(0xffffffffu, m, o));
    float sum = __expf(t0 - m) + __expf(t1 - m);
    #pragma unroll
    for (int o = 16; o > 0; o >>= 1) sum += __shfl_xor_sync(0xffffffffu, sum, o);
    float ls = m + __logf(sum);
    float2 r; r.x = t0 - ls; r.y = t1 - ls;
    *(float2*)(out + (size_t)w*CLS + lane*2) = r;
}

// ---------------- launch ----------------
extern "C" void kernel_launch(void* const* d_in, const int* in_sizes, int n_in,
                              void* d_out, int out_size)
{
    const float* x   = (const float*)d_in[0];
    const int*   src = (const int*)d_in[1];     // int32 (JAX x64 disabled)
    const int*   dst = (const int*)d_in[2];
    const float* W1  = (const float*)d_in[3];
    const float* b1  = (const float*)d_in[4];
    const float* W2  = (const float*)d_in[5];
    const float* b2  = (const float*)d_in[6];
    float* out = (float*)d_out;
    const int E = in_sizes[1];

    // idempotent attribute sets (host-side, not stream ops)
    cudaFuncSetAttribute(k_mma<128,128,32,256,1>,
                         cudaFuncAttributeMaxDynamicSharedMemorySize, MMA1_SMEM);
    cudaFuncSetAttribute(k_mma<128,64,32,256,2>,
                         cudaFuncAttributeMaxDynamicSharedMemorySize, MMA2_SMEM);

    const int nb256 = (N_NODES + 255)/256;
    const int e4    = (E/4 + 255)/256 + 1;
    const int sb    = (N_NODES + SCB - 1)/SCB;
    const int gx1   = (N_NODES + 127)/128;
    const int gwarp = (N_NODES*32 + 255)/256;

    // fork side stream
    cudaEventRecord(g_ss.fork, 0);
    cudaStreamWaitEvent(g_ss.s, g_ss.fork, 0);

    // mma1 at launch #4 (ncu capture window)
    k_zero <<<nb256, 256, 0, g_ss.s>>>();                       // #1 (side)
    k_hist <<<e4, 256, 0, g_ss.s>>>(dst, E);                    // #2 (side)
    k_prepw<<<(HID*F_IN + 255)/256, 256>>>(W1, W2);             // #3 (default)
    k_mma<128,128,32,256,1><<<gx1, 256, MMA1_SMEM>>>(x, N_NODES, F_IN); // #4
    k_scan1<<<sb, SCB, 0, g_ss.s>>>(N_NODES);
    k_scan2<<<1, 256, 0, g_ss.s>>>(sb);
    k_scan3<<<sb, SCB, 0, g_ss.s>>>(N_NODES, E);
    k_fill <<<e4, 256, 0, g_ss.s>>>(src, dst, E);
    cudaEventRecord(g_ss.join, g_ss.s);

    // join, then the dependent tail
    cudaStreamWaitEvent(0, g_ss.join, 0);
    k_gather1<<<gwarp, 256>>>(b1);
    k_mma<128,64,32,256,2><<<gx1, 256, MMA2_SMEM>>>(nullptr, N_NODES, HID);
    k_gather2<<<gwarp, 256>>>(out, b2);
}

// round 17
// speedup vs baseline: 1.5249x; 1.5249x over previous
#include <cuda_runtime.h>
#include <cuda_fp16.h>
#include <math.h>
#include <stdint.h>

#define N_NODES 100000
#define F_IN    512
#define HID     128
#define CLS     64
#define E_MAX   1600000

// ---------------- scratch (no cudaMalloc allowed) ----------------
__device__ __half g_h1h [(size_t)N_NODES * HID]; // h1 = x@W1 (UNSCALED), fp16
__device__ __half g_acc1[(size_t)N_NODES * HID]; // a1 = relu(inv*sum + b1), fp16
__device__ __half g_h2h [(size_t)N_NODES * CLS]; // g2 = inv*(a1@W2), fp16
__device__ __half g_W1t[(size_t)HID * F_IN];     // W1 transposed, n-major, fp16
__device__ __half g_W2t[(size_t)CLS * HID];      // W2 transposed, n-major, fp16
__device__ float  g_inv [N_NODES];
__device__ int    g_cnt [N_NODES];
__device__ int    g_rowstart[N_NODES + 1];
__device__ int    g_cursor[N_NODES];
__device__ int    g_blksum[256];
__device__ int    g_blkoff[256];
__device__ int    g_esrc[E_MAX];

// ---- side stream + fork/join events (static init; not device allocs) ----
struct SideStream {
    cudaStream_t s;
    cudaEvent_t  fork, join;
    SideStream() {
        cudaStreamCreateWithFlags(&s, cudaStreamNonBlocking);
        cudaEventCreateWithFlags(&fork, cudaEventDisableTiming);
        cudaEventCreateWithFlags(&join, cudaEventDisableTiming);
    }
};
static SideStream g_ss;

// ------- weight transpose/convert (default stream) -------
__global__ void k_prepw(const float* __restrict__ W1, const float* __restrict__ W2) {
    int i = blockIdx.x * blockDim.x + threadIdx.x;
    if (i < HID * F_IN) {
        int n = i / F_IN, k = i % F_IN;
        g_W1t[i] = __float2half(W1[(size_t)k * HID + n]);
    }
    if (i < CLS * HID) {
        int n = i / HID, k = i % HID;
        g_W2t[i] = __float2half(W2[(size_t)k * CLS + n]);
    }
}

// ---------------- CSR branch (side stream) ----------------
__global__ void k_zero() {
    int i = blockIdx.x * blockDim.x + threadIdx.x;
    if (i < N_NODES) g_cnt[i] = 0;
}
__global__ void k_hist(const int* __restrict__ dst, int E) {
    int i = (blockIdx.x * blockDim.x + threadIdx.x) * 4;
    if (i + 3 < E) {
        int4 d = *(const int4*)(dst + i);
        atomicAdd(&g_cnt[d.x], 1); atomicAdd(&g_cnt[d.y], 1);
        atomicAdd(&g_cnt[d.z], 1); atomicAdd(&g_cnt[d.w], 1);
    } else {
        for (; i < E; i++) atomicAdd(&g_cnt[dst[i]], 1);
    }
}

#define SCB 512
__global__ void k_scan1(int n) {
    __shared__ int wsum[16];
    int tid = threadIdx.x, lane = tid & 31, wid = tid >> 5;
    int i = blockIdx.x * SCB + tid;
    int v = (i < n) ? g_cnt[i] : 0;
    int x = v;
    #pragma unroll
    for (int o = 1; o < 32; o <<= 1) {
        int t = __shfl_up_sync(0xffffffffu, x, o);
        if (lane >= o) x += t;
    }
    if (lane == 31) wsum[wid] = x;
    __syncthreads();
    if (wid == 0) {
        int s = (lane < 16) ? wsum[lane] : 0;
        #pragma unroll
        for (int o = 1; o < 16; o <<= 1) {
            int t = __shfl_up_sync(0xffffffffu, s, o);
            if (lane >= o) s += t;
        }
        if (lane < 16) wsum[lane] = s;
    }
    __syncthreads();
    int base = (wid > 0) ? wsum[wid - 1] : 0;
    x += base;
    if (i < n) g_rowstart[i] = x - v;
    if (tid == SCB - 1) g_blksum[blockIdx.x] = x;
}
__global__ void k_scan2(int nb) {
    __shared__ int wsum[8];
    int tid = threadIdx.x, lane = tid & 31, wid = tid >> 5;
    int v = (tid < nb) ? g_blksum[tid] : 0;
    int x = v;
    #pragma unroll
    for (int o = 1; o < 32; o <<= 1) {
        int t = __shfl_up_sync(0xffffffffu, x, o);
        if (lane >= o) x += t;
    }
    if (lane == 31) wsum[wid] = x;
    __syncthreads();
    if (wid == 0) {
        int s = (lane < 8) ? wsum[lane] : 0;
        #pragma unroll
        for (int o = 1; o < 8; o <<= 1) {
            int t = __shfl_up_sync(0xffffffffu, s, o);
            if (lane >= o) s += t;
        }
        if (lane < 8) wsum[lane] = s;
    }
    __syncthreads();
    int base = (wid > 0) ? wsum[wid - 1] : 0;
    if (tid < nb) g_blkoff[tid] = x + base - v;
}
__global__ void k_scan3(int n, int E) {
    int i = blockIdx.x * blockDim.x + threadIdx.x;
    if (i < n) {
        int r = g_rowstart[i] + g_blkoff[i / SCB];
        g_rowstart[i] = r;
        g_cursor[i]   = r;
        g_inv[i]      = rsqrtf((float)(1 + g_cnt[i]));
    }
    if (i == 0) g_rowstart[n] = E;
}
__global__ void k_fill(const int* __restrict__ src, const int* __restrict__ dst, int E) {
    int i = (blockIdx.x * blockDim.x + threadIdx.x) * 4;
    if (i + 3 < E) {
        int4 s = *(const int4*)(src + i);
        int4 d = *(const int4*)(dst + i);
        g_esrc[atomicAdd(&g_cursor[d.x], 1)] = s.x;
        g_esrc[atomicAdd(&g_cursor[d.y], 1)] = s.y;
        g_esrc[atomicAdd(&g_cursor[d.z], 1)] = s.z;
        g_esrc[atomicAdd(&g_cursor[d.w], 1)] = s.w;
    } else {
        for (; i < E; i++) g_esrc[atomicAdd(&g_cursor[dst[i]], 1)] = src[i];
    }
}

// ---------------- fp16 mma m16n8k16 + ldmatrix + cp.async ----------------
__device__ __forceinline__ void mma_f16(float* c, uint32_t a0, uint32_t a1,
                                        uint32_t a2, uint32_t a3,
                                        uint32_t b0, uint32_t b1) {
    asm volatile(
        "mma.sync.aligned.m16n8k16.row.col.f32.f16.f16.f32 "
        "{%0,%1,%2,%3}, {%4,%5,%6,%7}, {%8,%9}, {%0,%1,%2,%3};"
        : "+f"(c[0]), "+f"(c[1]), "+f"(c[2]), "+f"(c[3])
        : "r"(a0), "r"(a1), "r"(a2), "r"(a3), "r"(b0), "r"(b1));
}
__device__ __forceinline__ void ldsm4(uint32_t& r0, uint32_t& r1,
                                      uint32_t& r2, uint32_t& r3, uint32_t a) {
    asm volatile("ldmatrix.sync.aligned.m8n8.x4.shared.b16 {%0,%1,%2,%3}, [%4];"
                 : "=r"(r0), "=r"(r1), "=r"(r2), "=r"(r3) : "r"(a));
}
__device__ __forceinline__ void cp16(void* dst, const void* src, bool pred) {
    uint32_t d = (uint32_t)__cvta_generic_to_shared(dst);
    int sz = pred ? 16 : 0;
    asm volatile("cp.async.cg.shared.global [%0],[%1],16,%2;"
                 :: "r"(d), "l"(src), "r"(sz));
}
__device__ __forceinline__ uint32_t packh2(float x, float y) {
    __half2 h = __floats2half2_rn(x, y);
    return *(uint32_t*)&h;
}

// ---- fp16 tensor-core GEMM, 3-stage cp.async pipeline, 2 CTAs/SM forced ----
// LAYER==1: A = x fp32 via cp.async (cvt at fragment build), out UNSCALED
// LAYER==2: A = g_acc1 fp16 via cp.async + ldmatrix, out scaled by inv[row]
template<int BM, int BN, int BK, int THREADS, int LAYER>
__global__ __launch_bounds__(THREADS, 2)          // <-- cap regs at 128: 2 CTAs/SM
void k_mma(const float* __restrict__ Ain, int M, int K)
{
    constexpr bool AH     = (LAYER == 2);
    constexpr int NWARP   = THREADS / 32;
    constexpr int WARPS_N = BN / 64;
    constexpr int WARPS_M = NWARP / WARPS_N;
    constexpr int WM      = BM / WARPS_M;      // 32
    constexpr int RT      = WM / 16;           // 2
    constexpr int PAD     = 8;
    constexpr int ASTR    = BK + PAD;          // elems (float L1, half L2)
    constexpr int BSTR    = BK + PAD;          // halves
    constexpr int STAGES  = 3;
    constexpr int A_STAGE = BM * ASTR * (AH ? 2 : 4);   // bytes
    constexpr int B_STAGE = BN * BSTR * 2;              // bytes
    constexpr int A_CP    = BM*BK*(AH?2:4)/16/THREADS;  // cp.async per thread
    constexpr int B_CP    = BN*BK*2/16/THREADS;

    extern __shared__ __align__(16) char smem_raw[];
    char* aPtr = smem_raw;
    char* bPtr = smem_raw + STAGES * A_STAGE;

    const __half* Asrc = (const __half*)g_acc1;
    const __half* Bt = (LAYER == 1) ? (const __half*)g_W1t : (const __half*)g_W2t;
    __half*       G  = (LAYER == 1) ? (__half*)g_h1h : (__half*)g_h2h;
    const int     N  = BN;

    const int tid  = threadIdx.x;
    const int warp = tid >> 5;
    const int lane = tid & 31;
    const int g    = lane >> 2;
    const int tg   = lane & 3;
    const int wr   = (warp / WARPS_N) * WM;
    const int wc   = (warp % WARPS_N) * 64;
    const int rowBase = blockIdx.x * BM;

    float acc[RT][8][4] = {};

    auto Af = [&](int st, int m, int k) -> float* {
        return (float*)(aPtr + st*A_STAGE) + m*ASTR + k;
    };
    auto Ahp = [&](int st, int m, int k) -> __half* {
        return (__half*)(aPtr + st*A_STAGE) + m*ASTR + k;
    };
    auto Bp = [&](int st, int n, int k) -> __half* {
        return (__half*)(bPtr + st*B_STAGE) + n*BSTR + k;
    };

    auto ldg_tiles = [&](int st, int k0) {
        if constexpr (!AH) {
            #pragma unroll
            for (int i = 0; i < A_CP; i++) {
                int id = tid + i*THREADS;
                int m = id / (BK/4), k4 = id % (BK/4);
                int row = rowBase + m;
                cp16(Af(st, m, k4*4), Ain + (size_t)row*K + k0 + k4*4, row < M);
            }
        } else {
            #pragma unroll
            for (int i = 0; i < A_CP; i++) {
                int id = tid + i*THREADS;
                int m = id / (BK/8), c8 = id % (BK/8);
                int row = rowBase + m;
                cp16(Ahp(st, m, c8*8), Asrc + (size_t)row*K + k0 + c8*8, row < M);
            }
        }
        #pragma unroll
        for (int i = 0; i < B_CP; i++) {
            int id = tid + i*THREADS;
            int n = id / (BK/8), c8 = id % (BK/8);
            cp16(Bp(st, n, c8*8), Bt + (size_t)n*K + k0 + c8*8, true);
        }
    };

    // ldmatrix bases per stage
    const int li = lane & 7, qd = lane >> 3;
    uint32_t bBase[STAGES], aBase[STAGES];
    #pragma unroll
    for (int st = 0; st < STAGES; st++) {
        bBase[st] = (uint32_t)__cvta_generic_to_shared(
            Bp(st, wc + (qd >> 1)*8 + li, (qd & 1)*8));
        if constexpr (AH)
            aBase[st] = (uint32_t)__cvta_generic_to_shared(
                Ahp(st, wr + (qd & 1)*8 + li, (qd >> 1)*8));
    }

    const int KT = K / BK;
    ldg_tiles(0, 0);
    asm volatile("cp.async.commit_group;");
    ldg_tiles(1, BK);
    asm volatile("cp.async.commit_group;");

    for (int kt = 0; kt < KT; kt++) {
        asm volatile("cp.async.wait_group 1;");
        __syncthreads();
        const int st = kt % STAGES;
        if (kt + 2 < KT) ldg_tiles((kt + 2) % STAGES, (kt + 2) * BK);
        asm volatile("cp.async.commit_group;");   // empty group OK at tail

        #pragma unroll
        for (int ks = 0; ks < BK/16; ks++) {
            const int k = ks*16;
            uint32_t bf[8][2];
            #pragma unroll
            for (int p = 0; p < 4; p++)
                ldsm4(bf[2*p][0], bf[2*p][1], bf[2*p+1][0], bf[2*p+1][1],
                      bBase[st] + (uint32_t)((p*16*BSTR + k) * 2));
            #pragma unroll
            for (int rt = 0; rt < RT; rt++) {
                const int r = wr + rt*16;
                uint32_t a0, a1, a2, a3;
                if constexpr (!AH) {
                    float2 f;
                    f = *(float2*)Af(st, r+g,   k + 2*tg);     a0 = packh2(f.x, f.y);
                    f = *(float2*)Af(st, r+g+8, k + 2*tg);     a1 = packh2(f.x, f.y);
                    f = *(float2*)Af(st, r+g,   k + 2*tg + 8); a2 = packh2(f.x, f.y);
                    f = *(float2*)Af(st, r+g+8, k + 2*tg + 8); a3 = packh2(f.x, f.y);
                } else {
                    ldsm4(a0, a1, a2, a3, aBase[st] + (uint32_t)((rt*16*ASTR + k) * 2));
                }
                #pragma unroll
                for (int j = 0; j < 8; j++)
                    mma_f16(acc[rt][j], a0, a1, a2, a3, bf[j][0], bf[j][1]);
            }
        }
        __syncthreads();
    }

    #pragma unroll
    for (int rt = 0; rt < RT; rt++) {
        int r0 = rowBase + wr + rt*16 + g;
        int r1 = r0 + 8;
        float s0, s1;
        if constexpr (LAYER == 1) { s0 = 1.f; s1 = 1.f; }
        else {
            s0 = (r0 < M) ? g_inv[r0] : 0.f;
            s1 = (r1 < M) ? g_inv[r1] : 0.f;
        }
        #pragma unroll
        for (int j = 0; j < 8; j++) {
            int col = wc + j*8 + tg*2;
            if (r0 < M) {
                __half2 v = __floats2half2_rn(acc[rt][j][0]*s0, acc[rt][j][1]*s0);
                *(__half2*)(G + (size_t)r0*N + col) = v;
            }
            if (r1 < M) {
                __half2 v = __floats2half2_rn(acc[rt][j][2]*s1, acc[rt][j][3]*s1);
                *(__half2*)(G + (size_t)r1*N + col) = v;
            }
        }
    }
}

// host-side smem sizes (match k_mma constants)
#define MMA1_SMEM (3 * (128*40*4 + 128*40*2))   // 92160 B
#define MMA2_SMEM (3 * (128*40*2 + 64*40*2))    // 46080 B

// ---------------- fp16 load helpers ----------------
__device__ __forceinline__ float4 ld_h4(const __half* p) {
    uint2 u = *(const uint2*)p;
    float2 a = __half22float2(*(__half2*)&u.x);
    float2 b = __half22float2(*(__half2*)&u.y);
    return make_float4(a.x, a.y, b.x, b.y);
}
__device__ __forceinline__ float2 ld_h2(const __half* p) {
    uint32_t u = *(const uint32_t*)p;
    return __half22float2(*(__half2*)&u);
}

// ---- gather layer 1: a1 = relu(inv[v]*(inv[v]*h[v] + sum inv[s]*h[s]) + b1)
__global__ void k_gather1(const float* __restrict__ b1) {
    int w    = (blockIdx.x * blockDim.x + threadIdx.x) >> 5;
    int lane = threadIdx.x & 31;
    if (w >= N_NODES) return;
    const __half* h = (const __half*)g_h1h;
    float wv = g_inv[w];
    float4 hv = ld_h4(h + (size_t)w*HID + lane*4);
    float4 acc;
    acc.x = wv*hv.x; acc.y = wv*hv.y; acc.z = wv*hv.z; acc.w = wv*hv.w;
    int i   = g_rowstart[w];
    int end = g_rowstart[w+1];
    for (; i + 7 < end; i += 8) {
        #pragma unroll
        for (int u = 0; u < 8; u++) {
            int s = g_esrc[i+u];
            float ws = g_inv[s];
            float4 v = ld_h4(h + (size_t)s*HID + lane*4);
            acc.x = fmaf(ws, v.x, acc.x); acc.y = fmaf(ws, v.y, acc.y);
            acc.z = fmaf(ws, v.z, acc.z); acc.w = fmaf(ws, v.w, acc.w);
        }
    }
    for (; i < end; i++) {
        int s = g_esrc[i];
        float ws = g_inv[s];
        float4 v = ld_h4(h + (size_t)s*HID + lane*4);
        acc.x = fmaf(ws, v.x, acc.x); acc.y = fmaf(ws, v.y, acc.y);
        acc.z = fmaf(ws, v.z, acc.z); acc.w = fmaf(ws, v.w, acc.w);
    }
    float4 bb = *(const float4*)(b1 + lane*4);
    __half2 h0 = __floats2half2_rn(fmaxf(fmaf(wv, acc.x, bb.x), 0.f),
                                   fmaxf(fmaf(wv, acc.y, bb.y), 0.f));
    __half2 h1 = __floats2half2_rn(fmaxf(fmaf(wv, acc.z, bb.z), 0.f),
                                   fmaxf(fmaf(wv, acc.w, bb.w), 0.f));
    uint2 u; u.x = *(uint32_t*)&h0; u.y = *(uint32_t*)&h1;
    *(uint2*)((__half*)g_acc1 + (size_t)w*HID + lane*4) = u;
}

// ---------------- gather layer 2 + log_softmax -> out ----------------------
__global__ void k_gather2(float* __restrict__ out, const float* __restrict__ b2) {
    int w    = (blockIdx.x * blockDim.x + threadIdx.x) >> 5;
    int lane = threadIdx.x & 31;
    if (w >= N_NODES) return;
    const __half* h = (const __half*)g_h2h;
    float2 acc = ld_h2(h + (size_t)w*CLS + lane*2);          // self (g2 scaled)
    int i   = g_rowstart[w];
    int end = g_rowstart[w+1];
    for (; i + 7 < end; i += 8) {
        #pragma unroll
        for (int u = 0; u < 8; u++) {
            int s = g_esrc[i+u];
            float2 v = ld_h2(h + (size_t)s*CLS + lane*2);
            acc.x += v.x; acc.y += v.y;
        }
    }
    for (; i < end; i++) {
        int s = g_esrc[i];
        float2 v = ld_h2(h + (size_t)s*CLS + lane*2);
        acc.x += v.x; acc.y += v.y;
    }
    float sc = g_inv[w];
    float t0 = fmaf(sc, acc.x, b2[lane*2+0]);
    float t1 = fmaf(sc, acc.y, b2[lane*2+1]);
    float m = fmaxf(t0, t1);
    #pragma unroll
    for (int o = 16; o > 0; o >>= 1) m = fmaxf(m, __shfl_xor_sync(0xffffffffu, m, o));
    float sum = __expf(t0 - m) + __expf(t1 - m);
    #pragma unroll
    for (int o = 16; o > 0; o >>= 1) sum += __shfl_xor_sync(0xffffffffu, sum, o);
    float ls = m + __logf(sum);
    float2 r; r.x = t0 - ls; r.y = t1 - ls;
    *(float2*)(out + (size_t)w*CLS + lane*2) = r;
}

// ---------------- launch ----------------
extern "C" void kernel_launch(void* const* d_in, const int* in_sizes, int n_in,
                              void* d_out, int out_size)
{
    const float* x   = (const float*)d_in[0];
    const int*   src = (const int*)d_in[1];     // int32 (JAX x64 disabled)
    const int*   dst = (const int*)d_in[2];
    const float* W1  = (const float*)d_in[3];
    const float* b1  = (const float*)d_in[4];
    const float* W2  = (const float*)d_in[5];
    const float* b2  = (const float*)d_in[6];
    float* out = (float*)d_out;
    const int E = in_sizes[1];

    cudaFuncSetAttribute(k_mma<128,128,32,256,1>,
                         cudaFuncAttributeMaxDynamicSharedMemorySize, MMA1_SMEM);
    cudaFuncSetAttribute(k_mma<128,64,32,256,2>,
                         cudaFuncAttributeMaxDynamicSharedMemorySize, MMA2_SMEM);

    const int nb256 = (N_NODES + 255)/256;
    const int e4    = (E/4 + 255)/256 + 1;
    const int sb    = (N_NODES + SCB - 1)/SCB;
    const int gx1   = (N_NODES + 127)/128;
    const int gwarp = (N_NODES*32 + 255)/256;

    // fork side stream
    cudaEventRecord(g_ss.fork, 0);
    cudaStreamWaitEvent(g_ss.s, g_ss.fork, 0);

    // mma1 at launch #4 (ncu capture window)
    k_zero <<<nb256, 256, 0, g_ss.s>>>();                       // #1 (side)
    k_hist <<<e4, 256, 0, g_ss.s>>>(dst, E);                    // #2 (side)
    k_prepw<<<(HID*F_IN + 255)/256, 256>>>(W1, W2);             // #3 (default)
    k_mma<128,128,32,256,1><<<gx1, 256, MMA1_SMEM>>>(x, N_NODES, F_IN); // #4
    k_scan1<<<sb, SCB, 0, g_ss.s>>>(N_NODES);
    k_scan2<<<1, 256, 0, g_ss.s>>>(sb);
    k_scan3<<<sb, SCB, 0, g_ss.s>>>(N_NODES, E);
    k_fill <<<e4, 256, 0, g_ss.s>>>(src, dst, E);
    cudaEventRecord(g_ss.join, g_ss.s);

    // join, then the dependent tail
    cudaStreamWaitEvent(0, g_ss.join, 0);
    k_gather1<<<gwarp, 256>>>(b1);
    k_mma<128,64,32,256,2><<<gx1, 256, MMA2_SMEM>>>(nullptr, N_NODES, HID);
    k_gather2<<<gwarp, 256>>>(out, b2);
}